// round 1
// baseline (speedup 1.0000x reference)
#include <cuda_runtime.h>

// Problem constants (from reference): B=32, P=3, D=300, N=2048
// x,y: [B,P,D,N] fp32.  For each (b,p,n): vector of length D strided by N.
// out: [B, P*N, 3] = {cos, l2, l1}.
//
// Strategy: one thread <-> 4 consecutive n (one float4). Loop over d (300),
// loads coalesced along n. 5 accumulators x 4 lanes. Pure HBM stream.

#define D_DIM 300
#define N_DIM 2048
#define N4 (N_DIM / 4)      // 512 float4 columns per (b,p) row
#define BP 96               // B*P
#define THREADS 128

__global__ __launch_bounds__(THREADS)
void sim_measure_kernel(const float* __restrict__ x,
                        const float* __restrict__ y,
                        float* __restrict__ out)
{
    const int idx = blockIdx.x * THREADS + threadIdx.x;   // global float4-column id
    // total float4 columns = BP * N4 = 96*512 = 49152
    const int n4 = idx & (N4 - 1);
    const int bp = idx >> 9;          // / 512

    const float4* __restrict__ xp =
        reinterpret_cast<const float4*>(x) + (size_t)bp * D_DIM * N4 + n4;
    const float4* __restrict__ yp =
        reinterpret_cast<const float4*>(y) + (size_t)bp * D_DIM * N4 + n4;

    float dot[4] = {0.f, 0.f, 0.f, 0.f};
    float xx [4] = {0.f, 0.f, 0.f, 0.f};
    float yy [4] = {0.f, 0.f, 0.f, 0.f};
    float dd [4] = {0.f, 0.f, 0.f, 0.f};
    float l1 [4] = {0.f, 0.f, 0.f, 0.f};

    #pragma unroll 4
    for (int d = 0; d < D_DIM; ++d) {
        const float4 a = __ldg(xp + (size_t)d * N4);
        const float4 b = __ldg(yp + (size_t)d * N4);

        const float ax[4] = {a.x, a.y, a.z, a.w};
        const float bx[4] = {b.x, b.y, b.z, b.w};
        #pragma unroll
        for (int j = 0; j < 4; ++j) {
            const float av = ax[j], bv = bx[j];
            dot[j] = fmaf(av, bv, dot[j]);
            xx [j] = fmaf(av, av, xx [j]);
            yy [j] = fmaf(bv, bv, yy [j]);
            const float df = av - bv;
            dd [j] = fmaf(df, df, dd [j]);
            l1 [j] += fabsf(df);
        }
    }

    // out layout: [bp, n, 3] -> offset (bp*N + n)*3
    const int n0 = n4 * 4;
    float* o = out + ((size_t)bp * N_DIM + n0) * 3;
    #pragma unroll
    for (int j = 0; j < 4; ++j) {
        const float cosv = dot[j] * rsqrtf(xx[j] * yy[j]);
        o[j * 3 + 0] = cosv;
        o[j * 3 + 1] = sqrtf(dd[j]);
        o[j * 3 + 2] = l1[j];
    }
}

extern "C" void kernel_launch(void* const* d_in, const int* in_sizes, int n_in,
                              void* d_out, int out_size)
{
    const float* x = (const float*)d_in[0];
    const float* y = (const float*)d_in[1];
    float* out = (float*)d_out;

    const int total_threads = BP * N4;          // 49152
    const int blocks = total_threads / THREADS; // 384
    sim_measure_kernel<<<blocks, THREADS>>>(x, y, out);
}

// round 2
// speedup vs baseline: 1.3349x; 1.3349x over previous
#include <cuda_runtime.h>

// B=32, P=3, D=300, N=2048.  x,y: [B,P,D,N] fp32.
// out: [B, P*N, 3] = {cos, l2, l1} per (b,p,n) vector of length D (stride N).
//
// One thread per (bp, n): scalar loads, coalesced along n within a warp.
// 196608 threads -> ~65% occupancy to hide DRAM latency (prev kernel was
// grid-limited at 15.6% occ, DRAM only 54.7%).

#define D_DIM 300
#define N_DIM 2048
#define BP 96
#define THREADS 256

__global__ __launch_bounds__(THREADS)
void sim_measure_kernel(const float* __restrict__ x,
                        const float* __restrict__ y,
                        float* __restrict__ out)
{
    const int idx = blockIdx.x * THREADS + threadIdx.x;   // 0 .. BP*N-1
    const int n  = idx & (N_DIM - 1);
    const int bp = idx >> 11;                             // / 2048

    const float* __restrict__ xp = x + (size_t)bp * D_DIM * N_DIM + n;
    const float* __restrict__ yp = y + (size_t)bp * D_DIM * N_DIM + n;

    float dot = 0.f, xx = 0.f, yy = 0.f, dd = 0.f, l1 = 0.f;

    #pragma unroll 5
    for (int d = 0; d < D_DIM; ++d) {
        const float av = __ldg(xp + (size_t)d * N_DIM);
        const float bv = __ldg(yp + (size_t)d * N_DIM);
        dot = fmaf(av, bv, dot);
        xx  = fmaf(av, av, xx);
        yy  = fmaf(bv, bv, yy);
        const float df = av - bv;
        dd  = fmaf(df, df, dd);
        l1 += fabsf(df);
    }

    // out layout: [bp, n, 3]
    float* o = out + ((size_t)bp * N_DIM + n) * 3;
    o[0] = dot * rsqrtf(xx * yy);
    o[1] = sqrtf(dd);
    o[2] = l1;
}

extern "C" void kernel_launch(void* const* d_in, const int* in_sizes, int n_in,
                              void* d_out, int out_size)
{
    const float* x = (const float*)d_in[0];
    const float* y = (const float*)d_in[1];
    float* out = (float*)d_out;

    const int total_threads = BP * N_DIM;        // 196608
    const int blocks = total_threads / THREADS;  // 768
    sim_measure_kernel<<<blocks, THREADS>>>(x, y, out);
}